// round 17
// baseline (speedup 1.0000x reference)
#include <cuda_runtime.h>
#include <cuda_bf16.h>
#include <cstdint>

// ---------------------------------------------------------------------------
// Round 17: x-GEMM hoisted out of the recurrence.
//  prep_x   : split x into bf16 hi/lo planes.
//  gemm_gx  : gates_x[s] = x[s] @ W_ih^T + b  (3-pass bf16-split, same lane
//             layout as the recurrent kernel), written in FRAGMENT layout:
//             g_gx[s][g][slice][thread(256)][16 fp32]  (1 GB, exact handoff).
//  lstm_mma : recurrent loop now h-only: d init = 4x LDG.128 of gx, then
//             16 kt h-MMAs (split halves), epilogue, staged publish. R14's
//             exchange warp / flags / copyout machinery unchanged.
// Geometry: 16 batch-groups (M=32) x 8 slices (N=128) = 128 CTAs, 1/SM,
// 288 threads = 8 compute warps + 1 exchange warp.
// ---------------------------------------------------------------------------

#define SEQ     512
#define BATCH   512
#define INPUT   128
#define HIDDEN  256
#define NGROUP  16
#define NSLICE  8
#define NCTA    128
#define NTHR    288
#define MR      32
#define NC      128

// ---- recurrent kernel smem (h-only, K=256) ----
#define HPITCH  528
#define BLO_O   0             // B_lo: 128 cols x 528 = 67584
#define HB0     67584         // h: 2 bufs x (hi 16896 + lo 16896) = 67584
#define HBSTRIDE 33792
#define HLOFF   16896
#define HSTG    135168        // staging: 2 planes x 32 rows x 80
#define HSTG_PITCH 80
#define HSTG_LO 2560
#define SMEM_BYTES 140288

// ---- precompute kernel smem (K=128) ----
#define PXP     272
#define PB_LO   0             // B_lo: 128 cols x 272 = 34816
#define PA      34816         // x tile: hi 8704 + lo 8704 (also B_hi stage)
#define PALO    43520
#define SMEM_P  52224

__device__ __align__(16) __nv_bfloat16 g_xhi[SEQ * BATCH * INPUT];
__device__ __align__(16) __nv_bfloat16 g_xlo[SEQ * BATCH * INPUT];
__device__ __align__(16) __nv_bfloat16 g_hh[2][NGROUP][MR][HIDDEN];
__device__ __align__(16) __nv_bfloat16 g_hl[2][NGROUP][MR][HIDDEN];
__device__ int g_flag[NGROUP][NSLICE][32];
// Precomputed x-part gates in fragment layout: [s][g][slice][thread][16]
__device__ float g_gx[(size_t)SEQ * NGROUP * NSLICE * 256 * 16];

// ---------------------------------------------------------------------------
__device__ __forceinline__ uint32_t smem_u32(const void* p) {
    uint32_t a;
    asm("{ .reg .u64 t; cvta.to.shared.u64 t, %1; cvt.u32.u64 %0, t; }"
        : "=r"(a) : "l"(p));
    return a;
}
__device__ __forceinline__ void ldsm4(uint32_t* r, uint32_t addr) {
    asm volatile("ldmatrix.sync.aligned.m8n8.x4.shared.b16 {%0,%1,%2,%3}, [%4];"
        : "=r"(r[0]), "=r"(r[1]), "=r"(r[2]), "=r"(r[3]) : "r"(addr));
}
__device__ __forceinline__ void ldsm2(uint32_t* r, uint32_t addr) {
    asm volatile("ldmatrix.sync.aligned.m8n8.x2.shared.b16 {%0,%1}, [%2];"
        : "=r"(r[0]), "=r"(r[1]) : "r"(addr));
}
__device__ __forceinline__ void mma_bf16(float* d, const uint32_t* a,
                                         const uint32_t* b) {
    asm volatile("mma.sync.aligned.m16n8k16.row.col.f32.bf16.bf16.f32 "
        "{%0,%1,%2,%3}, {%4,%5,%6,%7}, {%8,%9}, {%0,%1,%2,%3};"
        : "+f"(d[0]), "+f"(d[1]), "+f"(d[2]), "+f"(d[3])
        : "r"(a[0]), "r"(a[1]), "r"(a[2]), "r"(a[3]), "r"(b[0]), "r"(b[1]));
}
__device__ __forceinline__ void cpasync16(uint32_t dst, const void* src) {
    asm volatile("cp.async.cg.shared.global [%0], [%1], 16;"
        :: "r"(dst), "l"(src));
}
#define CP_COMMIT() asm volatile("cp.async.commit_group;" ::: "memory")
#define CP_WAIT0()  asm volatile("cp.async.wait_group 0;" ::: "memory")
#define CP_WAIT1()  asm volatile("cp.async.wait_group 1;" ::: "memory")

#define BAR_SYNC(id, n)   asm volatile("bar.sync %0, %1;" :: "r"(id), "r"(n) : "memory")
#define BAR_ARRIVE(id, n) asm volatile("bar.arrive %0, %1;" :: "r"(id), "r"(n) : "memory")

__device__ __forceinline__ void st_release(int* p, int v) {
    asm volatile("st.release.gpu.global.b32 [%0], %1;" :: "l"(p), "r"(v) : "memory");
}
__device__ __forceinline__ int ld_acquire(const int* p) {
    int v;
    asm volatile("ld.acquire.gpu.global.u32 %0, [%1];" : "=r"(v) : "l"(p) : "memory");
    return v;
}

__device__ __forceinline__ float sigf(float v)  { return 1.0f / (1.0f + __expf(-v)); }
__device__ __forceinline__ float tanhx(float v) { return 2.0f / (1.0f + __expf(-2.0f * v)) - 1.0f; }
__device__ __forceinline__ uint32_t pk2(float a, float b) {
    __nv_bfloat162 t = __floats2bfloat162_rn(a, b);
    return *reinterpret_cast<uint32_t*>(&t);
}
// Gate-interleaved column map: n = 16nq+8nt+2q+e -> gate(2nt+e), unit(4nq+q)
__device__ __forceinline__ int map_gcol(int n, int slice) {
    int nq = n >> 4, nt = (n >> 3) & 1, q = (n >> 1) & 3, e = n & 1;
    return (2 * nt + e) * HIDDEN + slice * 32 + (4 * nq + q);
}

// ---------------------------------------------------------------------------
__global__ void prep_x(const float* __restrict__ x) {
    const int N4 = SEQ * BATCH * INPUT / 4;
    for (int i = blockIdx.x * blockDim.x + threadIdx.x; i < N4;
         i += gridDim.x * blockDim.x) {
        float4 v = *reinterpret_cast<const float4*>(x + 4 * i);
        float hx = __bfloat162float(__float2bfloat16(v.x));
        float hy = __bfloat162float(__float2bfloat16(v.y));
        float hz = __bfloat162float(__float2bfloat16(v.z));
        float hw = __bfloat162float(__float2bfloat16(v.w));
        uint2 hi, lo;
        hi.x = pk2(v.x, v.y); hi.y = pk2(v.z, v.w);
        lo.x = pk2(v.x - hx, v.y - hy); lo.y = pk2(v.z - hz, v.w - hw);
        reinterpret_cast<uint2*>(g_xhi)[i] = hi;
        reinterpret_cast<uint2*>(g_xlo)[i] = lo;
    }
}

// ---------------------------------------------------------------------------
// Precompute: gates_x = x @ W_ih^T + bias (3-pass), fragment-layout output.
// grid = 128 step-chunks x 16 groups x 8 slices = 16384 CTAs, 256 threads.
// ---------------------------------------------------------------------------
__global__ void __launch_bounds__(256)
gemm_gx(const float* __restrict__ W_ih,
        const float* __restrict__ b_ih, const float* __restrict__ b_hh) {
    extern __shared__ char smem[];
    const uint32_t sA = smem_u32(smem);
    const int tid  = threadIdx.x;
    const int wid  = tid >> 5;
    const int lane = tid & 31;
    const int b     = blockIdx.x;
    const int slice = b & 7;
    const int g     = (b >> 3) & 15;
    const int sc    = b >> 7;            // 0..127 -> steps 4sc..4sc+3
    const int nq = wid;
    const int l15 = lane & 15;

    // B_lo (K=128): cols gate-interleaved
    for (int i = tid; i < NC * INPUT; i += 256) {
        int n = i >> 7, k = i & 127;
        int gcol = map_gcol(n, slice);
        float wv = W_ih[(size_t)gcol * INPUT + k];
        __nv_bfloat16 bhv = __float2bfloat16(wv);
        __nv_bfloat16 blv = __float2bfloat16(wv - __bfloat162float(bhv));
        *reinterpret_cast<__nv_bfloat16*>(smem + PB_LO + n * PXP + 2 * k) = blv;
    }
    // B_hi -> regs, 2 phases of 64 cols staged in PA region
    uint32_t bh[8][2][2];
    #pragma unroll
    for (int p = 0; p < 2; ++p) {
        __syncthreads();
        for (int i = tid; i < 64 * INPUT; i += 256) {
            int n = i >> 7, k = i & 127;
            int gcol = map_gcol(p * 64 + n, slice);
            *reinterpret_cast<__nv_bfloat16*>(smem + PA + n * PXP + 2 * k) =
                __float2bfloat16(W_ih[(size_t)gcol * INPUT + k]);
        }
        __syncthreads();
        if ((nq >> 2) == p) {
            int nloc = 16 * (nq & 3);
            uint32_t base = sA + PA + (uint32_t)(nloc + (l15 & 7)) * PXP
                          + (uint32_t)((l15 >> 3) & 1) * 16;
            #pragma unroll
            for (int kt = 0; kt < 8; ++kt) {
                ldsm2(&bh[kt][0][0], base + kt * 32);
                ldsm2(&bh[kt][1][0], base + 8 * PXP + kt * 32);
            }
        }
    }
    __syncthreads();

    // bias
    const int q = lane & 3;
    const int gunit = slice * 32 + 4 * nq + q;
    float cb[2][2];
    #pragma unroll
    for (int nt = 0; nt < 2; ++nt)
        #pragma unroll
        for (int e = 0; e < 2; ++e) {
            int gcol = (2 * nt + e) * HIDDEN + gunit;
            cb[nt][e] = b_ih[gcol] + b_hh[gcol];
        }

    const uint32_t baseX  = sA + PA + (uint32_t)l15 * PXP
                          + (uint32_t)(lane >> 4) * 16;
    const uint32_t baseBL = sA + PB_LO + (uint32_t)(16 * nq + (l15 & 7)) * PXP
                          + (uint32_t)((l15 >> 3) & 1) * 16;

    for (int ss = 0; ss < 4; ++ss) {
        const int s = 4 * sc + ss;
        // stage x(s) rows g*32..+31 (hi/lo)
        const __nv_bfloat16* xh_ = g_xhi + ((size_t)s * BATCH + g * MR) * INPUT;
        const __nv_bfloat16* xl_ = g_xlo + ((size_t)s * BATCH + g * MR) * INPUT;
        for (int i = tid; i < MR * 16; i += 256) {
            int r = i >> 4, ch = i & 15;
            uint32_t dst = sA + PA + r * PXP + ch * 16;
            cpasync16(dst, xh_ + r * INPUT + ch * 8);
            cpasync16(dst + (PALO - PA), xl_ + r * INPUT + ch * 8);
        }
        CP_COMMIT();
        CP_WAIT0();
        __syncthreads();

        float d[2][2][4];
        #pragma unroll
        for (int mt = 0; mt < 2; ++mt)
            #pragma unroll
            for (int nt = 0; nt < 2; ++nt) {
                d[mt][nt][0] = cb[nt][0]; d[mt][nt][1] = cb[nt][1];
                d[mt][nt][2] = cb[nt][0]; d[mt][nt][3] = cb[nt][1];
            }
        #pragma unroll
        for (int kt = 0; kt < 8; ++kt) {
            uint32_t ah0[4], ah1[4], al0[4], al1[4], b0[2], b1[2];
            ldsm4(ah0, baseX + kt * 32);
            ldsm4(ah1, baseX + 16 * PXP + kt * 32);
            ldsm4(al0, baseX + (PALO - PA) + kt * 32);
            ldsm4(al1, baseX + (PALO - PA) + 16 * PXP + kt * 32);
            ldsm2(b0, baseBL + kt * 32);
            ldsm2(b1, baseBL + 8 * PXP + kt * 32);
            mma_bf16(d[0][0], ah0, bh[kt][0]); mma_bf16(d[0][1], ah0, bh[kt][1]);
            mma_bf16(d[1][0], ah1, bh[kt][0]); mma_bf16(d[1][1], ah1, bh[kt][1]);
            mma_bf16(d[0][0], al0, bh[kt][0]); mma_bf16(d[0][1], al0, bh[kt][1]);
            mma_bf16(d[1][0], al1, bh[kt][0]); mma_bf16(d[1][1], al1, bh[kt][1]);
            mma_bf16(d[0][0], ah0, b0); mma_bf16(d[0][1], ah0, b1);
            mma_bf16(d[1][0], ah1, b0); mma_bf16(d[1][1], ah1, b1);
        }
        // store in fragment layout: 4x float4 per thread, coalesced
        float4* outp = reinterpret_cast<float4*>(
            g_gx + ((((size_t)s * NGROUP + g) * NSLICE + slice) * 256 + tid) * 16);
        #pragma unroll
        for (int mt = 0; mt < 2; ++mt)
            #pragma unroll
            for (int nt = 0; nt < 2; ++nt)
                outp[mt * 2 + nt] = make_float4(d[mt][nt][0], d[mt][nt][1],
                                                d[mt][nt][2], d[mt][nt][3]);
        __syncthreads();   // before next ss overwrites PA
    }
}

// ---------------------------------------------------------------------------
__global__ void __launch_bounds__(NTHR, 1)
lstm_mma(const float* __restrict__ W_hh, const float* __restrict__ W_out,
         const float* __restrict__ b_out, float* __restrict__ out) {
    extern __shared__ char smem[];
    const uint32_t sA = smem_u32(smem);

    const int tid  = threadIdx.x;
    const int wid  = tid >> 5;
    const int lane = tid & 31;
    const int g     = blockIdx.x >> 3;
    const int slice = blockIdx.x & 7;
    const bool is_x = (wid == 8);
    const int nq = wid;
    const int l15 = lane & 15;

    // ---- B_lo (h-part, K=256) gate-interleaved ----
    for (int i = tid; i < NC * HIDDEN; i += NTHR) {
        int n = i >> 8, hk = i & 255;
        int gcol = map_gcol(n, slice);
        float wv = W_hh[(size_t)gcol * HIDDEN + hk];
        __nv_bfloat16 bhv = __float2bfloat16(wv);
        __nv_bfloat16 blv = __float2bfloat16(wv - __bfloat162float(bhv));
        *reinterpret_cast<__nv_bfloat16*>(smem + BLO_O + n * HPITCH + 2 * hk) = blv;
    }
    // ---- B_hi -> compute-warp regs, 2 phases of 64 cols (stage in HB0) ----
    uint32_t bh[16][2][2];
    #pragma unroll
    for (int p = 0; p < 2; ++p) {
        __syncthreads();
        for (int i = tid; i < 64 * HIDDEN; i += NTHR) {
            int n = i >> 8, hk = i & 255;
            int gcol = map_gcol(p * 64 + n, slice);
            *reinterpret_cast<__nv_bfloat16*>(smem + HB0 + n * HPITCH + 2 * hk) =
                __float2bfloat16(W_hh[(size_t)gcol * HIDDEN + hk]);
        }
        __syncthreads();
        if (!is_x && (nq >> 2) == p) {
            int nloc = 16 * (nq & 3);
            uint32_t base = sA + HB0 + (uint32_t)(nloc + (l15 & 7)) * HPITCH
                          + (uint32_t)((l15 >> 3) & 1) * 16;
            #pragma unroll
            for (int kt = 0; kt < 16; ++kt) {
                ldsm2(&bh[kt][0][0], base + kt * 32);
                ldsm2(&bh[kt][1][0], base + 8 * HPITCH + kt * 32);
            }
        }
    }
    __syncthreads();
    // ---- zero h buffer 0 (h = 0 at step 0) ----
    for (int i = tid; i < HBSTRIDE / 4; i += NTHR)
        reinterpret_cast<uint32_t*>(smem + HB0)[i] = 0;
    __syncthreads();

    if (is_x) {
        // =================== EXCHANGE WARP ===================
        for (int s = 0; s < SEQ; ++s) {
            const int tag = s & 1;
            const __nv_bfloat16* hh = &g_hh[(s - 1) & 1][g][0][0];
            const __nv_bfloat16* hl = &g_hl[(s - 1) & 1][g][0][0];
            uint32_t hb = sA + HB0 + (uint32_t)(s & 1) * HBSTRIDE;

            if (s > 0) {   // half A: producers 0..3 (units 0..127)
                if (lane < 4)
                    while (ld_acquire(&g_flag[g][lane][0]) != tag) __nanosleep(16);
                __syncwarp();
                for (int i = lane; i < MR * 16; i += 32) {
                    int r = i >> 4, ch = i & 15;
                    uint32_t dst = hb + r * HPITCH + ch * 16;
                    cpasync16(dst, hh + r * HIDDEN + ch * 8);
                    cpasync16(dst + HLOFF, hl + r * HIDDEN + ch * 8);
                }
            }
            CP_COMMIT();     // group h1

            if (s > 0) {   // half B: producers 4..7 (units 128..255)
                if (lane < 4)
                    while (ld_acquire(&g_flag[g][4 + lane][0]) != tag) __nanosleep(16);
                __syncwarp();
                for (int i = lane; i < MR * 16; i += 32) {
                    int r = i >> 4, ch = 16 + (i & 15);
                    uint32_t dst = hb + r * HPITCH + ch * 16;
                    cpasync16(dst, hh + r * HIDDEN + ch * 8);
                    cpasync16(dst + HLOFF, hl + r * HIDDEN + ch * 8);
                }
            }
            CP_COMMIT();     // group h2

            CP_WAIT1();                  // h1 landed
            BAR_ARRIVE(3, NTHR);         // compute may run kt 0..7
            CP_WAIT0();                  // h2 landed
            BAR_ARRIVE(1, NTHR);         // compute may run kt 8..15
            BAR_SYNC(2, NTHR);           // compute epilogue + copy-out done
            if (lane == 0) {
                __threadfence();
                st_release(&g_flag[g][slice][0], tag ^ 1);
            }
            __syncwarp();
        }
        if (lane < 8)
            while (ld_acquire(&g_flag[g][lane][0]) != 0) __nanosleep(16);
        __syncwarp();
    } else {
        // =================== COMPUTE WARPS ===================
        const uint32_t baseH  = sA + HB0 + (uint32_t)l15 * HPITCH
                              + (uint32_t)(lane >> 4) * 16;
        const uint32_t baseBL = sA + BLO_O + (uint32_t)(16 * nq + (l15 & 7)) * HPITCH
                              + (uint32_t)((l15 >> 3) & 1) * 16;

        const int q = lane & 3;
        const int unit_l = 4 * nq + q;
        const int gunit = slice * 32 + unit_l;
        const float4* gxp = reinterpret_cast<const float4*>(
            g_gx + (((size_t)g * NSLICE + slice) * 256 + tid) * 16);
        const size_t gx_step = (size_t)NGROUP * NSLICE * 256 * 4; // float4 units

        float cst[4] = {0.f, 0.f, 0.f, 0.f};

        for (int s = 0; s < SEQ; ++s) {
            // ---- d init from precomputed gates_x (coalesced LDG.128) ----
            float d[2][2][4];
            {
                const float4* p = gxp + (size_t)s * gx_step;
                float4 v0 = __ldg(p + 0), v1 = __ldg(p + 1);
                float4 v2 = __ldg(p + 2), v3 = __ldg(p + 3);
                d[0][0][0]=v0.x; d[0][0][1]=v0.y; d[0][0][2]=v0.z; d[0][0][3]=v0.w;
                d[0][1][0]=v1.x; d[0][1][1]=v1.y; d[0][1][2]=v1.z; d[0][1][3]=v1.w;
                d[1][0][0]=v2.x; d[1][0][1]=v2.y; d[1][0][2]=v2.z; d[1][0][3]=v2.w;
                d[1][1][0]=v3.x; d[1][1][1]=v3.y; d[1][1][2]=v3.z; d[1][1][3]=v3.w;
            }

            uint32_t bhm = baseH + (uint32_t)(s & 1) * HBSTRIDE;

            BAR_SYNC(3, NTHR);   // first half of h(s-1) staged

            #pragma unroll
            for (int kt = 0; kt < 8; ++kt) {
                uint32_t ah0[4], ah1[4], al0[4], al1[4], b0[2], b1[2];
                uint32_t ko = kt * 32;
                ldsm4(ah0, bhm + ko);
                ldsm4(ah1, bhm + 16 * HPITCH + ko);
                ldsm4(al0, bhm + HLOFF + ko);
                ldsm4(al1, bhm + HLOFF + 16 * HPITCH + ko);
                ldsm2(b0, baseBL + ko);
                ldsm2(b1, baseBL + 8 * HPITCH + ko);
                mma_bf16(d[0][0], ah0, bh[kt][0]); mma_bf16(d[0][1], ah0, bh[kt][1]);
                mma_bf16(d[1][0], ah1, bh[kt][0]); mma_bf16(d[1][1], ah1, bh[kt][1]);
                mma_bf16(d[0][0], al0, bh[kt][0]); mma_bf16(d[0][1], al0, bh[kt][1]);
                mma_bf16(d[1][0], al1, bh[kt][0]); mma_bf16(d[1][1], al1, bh[kt][1]);
                mma_bf16(d[0][0], ah0, b0); mma_bf16(d[0][1], ah0, b1);
                mma_bf16(d[1][0], ah1, b0); mma_bf16(d[1][1], ah1, b1);
            }

            BAR_SYNC(1, NTHR);   // second half staged

            #pragma unroll
            for (int kt = 8; kt < 16; ++kt) {
                uint32_t ah0[4], ah1[4], al0[4], al1[4], b0[2], b1[2];
                uint32_t ko = kt * 32;
                ldsm4(ah0, bhm + ko);
                ldsm4(ah1, bhm + 16 * HPITCH + ko);
                ldsm4(al0, bhm + HLOFF + ko);
                ldsm4(al1, bhm + HLOFF + 16 * HPITCH + ko);
                ldsm2(b0, baseBL + ko);
                ldsm2(b1, baseBL + 8 * HPITCH + ko);
                mma_bf16(d[0][0], ah0, bh[kt][0]); mma_bf16(d[0][1], ah0, bh[kt][1]);
                mma_bf16(d[1][0], ah1, bh[kt][0]); mma_bf16(d[1][1], ah1, bh[kt][1]);
                mma_bf16(d[0][0], al0, bh[kt][0]); mma_bf16(d[0][1], al0, bh[kt][1]);
                mma_bf16(d[1][0], al1, bh[kt][0]); mma_bf16(d[1][1], al1, bh[kt][1]);
                mma_bf16(d[0][0], ah0, b0); mma_bf16(d[0][1], ah0, b1);
                mma_bf16(d[1][0], ah1, b0); mma_bf16(d[1][1], ah1, b1);
            }

            // ---- in-register epilogue -> smem stage (bf16 hi/lo) ----
            #pragma unroll
            for (int mt = 0; mt < 2; ++mt)
                #pragma unroll
                for (int h2 = 0; h2 < 2; ++h2) {
                    float iv = d[mt][0][2 * h2 + 0];
                    float fv = d[mt][0][2 * h2 + 1];
                    float gv = d[mt][1][2 * h2 + 0];
                    float ov = d[mt][1][2 * h2 + 1];
                    int ci = 2 * mt + h2;
                    cst[ci] = sigf(fv) * cst[ci] + sigf(iv) * tanhx(gv);
                    float hn = sigf(ov) * tanhx(cst[ci]);
                    __nv_bfloat16 hb16 = __float2bfloat16(hn);
                    __nv_bfloat16 lb16 = __float2bfloat16(hn - __bfloat162float(hb16));
                    int r = 16 * mt + 8 * h2 + (lane >> 2);
                    *reinterpret_cast<__nv_bfloat16*>(
                        smem + HSTG + r * HSTG_PITCH + 2 * unit_l) = hb16;
                    *reinterpret_cast<__nv_bfloat16*>(
                        smem + HSTG + HSTG_LO + r * HSTG_PITCH + 2 * unit_l) = lb16;
                }

            BAR_SYNC(4, 256);    // compute-only: stage complete

            // ---- coalesced copy-out: 256 threads x one 16B chunk ----
            {
                int plane = tid >> 7;
                int idx = tid & 127;
                int row = idx >> 2;
                int cpos = idx & 3;
                uint4 v = *reinterpret_cast<const uint4*>(
                    smem + HSTG + plane * HSTG_LO + row * HSTG_PITCH + cpos * 16);
                __nv_bfloat16* dst = plane
                    ? &g_hl[s & 1][g][row][slice * 32 + cpos * 8]
                    : &g_hh[s & 1][g][row][slice * 32 + cpos * 8];
                __stcg(reinterpret_cast<uint4*>(dst), v);
            }

            BAR_ARRIVE(2, NTHR);   // exchange warp publishes flag
        }
    }

    __syncthreads();

    // ---- final projection (slice 0, compute warps) ----
    if (slice == 0 && !is_x) {
        const int buf = (SEQ - 1) & 1;
        const float bo = b_out[0];
        for (int r4 = 0; r4 < 4; ++r4) {
            int r = wid * 4 + r4;
            int c0 = lane * 8;
            uint4 hv = __ldcg(reinterpret_cast<const uint4*>(&g_hh[buf][g][r][c0]));
            uint4 lv = __ldcg(reinterpret_cast<const uint4*>(&g_hl[buf][g][r][c0]));
            float acc = 0.0f;
            const uint32_t* hp = &hv.x;
            const uint32_t* lp = &lv.x;
            #pragma unroll
            for (int qq = 0; qq < 4; ++qq) {
                float2 h2 = __bfloat1622float2(*reinterpret_cast<const __nv_bfloat162*>(&hp[qq]));
                float2 l2 = __bfloat1622float2(*reinterpret_cast<const __nv_bfloat162*>(&lp[qq]));
                acc += (h2.x + l2.x) * W_out[c0 + 2 * qq]
                     + (h2.y + l2.y) * W_out[c0 + 2 * qq + 1];
            }
            #pragma unroll
            for (int off = 16; off > 0; off >>= 1)
                acc += __shfl_xor_sync(0xFFFFFFFFu, acc, off);
            if (lane == 0) out[g * MR + r] = acc + bo;
        }
    }
}

// ---------------------------------------------------------------------------
extern "C" void kernel_launch(void* const* d_in, const int* in_sizes, int n_in,
                              void* d_out, int out_size) {
    const float* x     = (const float*)d_in[0];
    const float* W_ih  = (const float*)d_in[1];
    const float* W_hh  = (const float*)d_in[2];
    const float* b_ih  = (const float*)d_in[3];
    const float* b_hh  = (const float*)d_in[4];
    const float* W_out = (const float*)d_in[5];
    const float* b_out = (const float*)d_in[6];
    float* out = (float*)d_out;

    prep_x<<<2048, 256>>>(x);
    cudaFuncSetAttribute(gemm_gx,
                         cudaFuncAttributeMaxDynamicSharedMemorySize, SMEM_P);
    gemm_gx<<<16384, 256, SMEM_P>>>(W_ih, b_ih, b_hh);
    cudaFuncSetAttribute(lstm_mma,
                         cudaFuncAttributeMaxDynamicSharedMemorySize, SMEM_BYTES);
    lstm_mma<<<NCTA, NTHR, SMEM_BYTES>>>(W_hh, W_out, b_out, out);
}